// round 2
// baseline (speedup 1.0000x reference)
#include <cuda_runtime.h>
#include <math.h>

#define BB   8
#define TT   150
#define DD   30
#define HH   5
#define HDD  6
#define LL   3
#define NI   40     // BB*HH
#define KL   300
#define KA   74
#define KV   35
#define AA   6      // a-values per attention block (3 f32x2 pairs)

// ---------------- device scratch (no allocations allowed) ----------------
__device__ float g_mod[3][TT*BB*DD];          // 0: pl, 1: pa, 2: pv   [T,B,D]
__device__ float g_h[2][TT*BB*DD];            // per-stream hidden state [T,B,D]
__device__ float g_K[2][LL][NI*TT*HDD];       // per (s,l): [i, t, e]
__device__ float g_V[2][LL][NI*TT*HDD];
__device__ float g_vbar[2][LL][NI*HDD];
__device__ float g_Q[2][NI*TT*HDD];           // current-layer Q
__device__ float g_attn[2][TT*BB*DD];         // attention output [T,B,D]

__device__ __forceinline__ float warpsum(float v){
    #pragma unroll
    for (int o=16;o>0;o>>=1) v += __shfl_xor_sync(0xffffffffu, v, o);
    return v;
}
__device__ __forceinline__ unsigned long long pack2(float lo, float hi){
    unsigned long long d;
    asm("mov.b64 %0, {%1, %2};" : "=l"(d) : "f"(lo), "f"(hi));
    return d;
}
__device__ __forceinline__ void unpack2(unsigned long long v, float& lo, float& hi){
    asm("mov.b64 {%0, %1}, %2;" : "=f"(lo), "=f"(hi) : "l"(v));
}
__device__ __forceinline__ unsigned long long mul2(unsigned long long a, unsigned long long b){
    unsigned long long d;
    asm("mul.rn.f32x2 %0, %1, %2;" : "=l"(d) : "l"(a), "l"(b));
    return d;
}
__device__ __forceinline__ unsigned long long fma2(unsigned long long a, unsigned long long b, unsigned long long c){
    unsigned long long d;
    asm("fma.rn.f32x2 %0, %1, %2, %3;" : "=l"(d) : "l"(a), "l"(b), "l"(c));
    return d;
}

// ---------------- 1. modality projections (conv1d k=1), warp-per-row -----
__global__ void k_proj(const float* __restrict__ xl, const float* __restrict__ xa,
                       const float* __restrict__ xv, const float* __restrict__ Wl,
                       const float* __restrict__ Wa, const float* __restrict__ Wv){
    int w = threadIdx.x >> 5, lane = threadIdx.x & 31;
    int r = blockIdx.x*4 + w;            // 0..T*B-1
    int mod = blockIdx.y;                // 0,1,2
    int t = r / BB, b = r % BB;
    const float *x, *W; int K;
    if (mod==0){x=xl;W=Wl;K=KL;} else if (mod==1){x=xa;W=Wa;K=KA;} else {x=xv;W=Wv;K=KV;}
    __shared__ float sx[4][KL];
    const float* xr = x + (b*TT + t)*K;
    for (int k=lane; k<K; k+=32) sx[w][k]=xr[k];
    __syncwarp();
    if (lane < DD){
        float acc = 0.f;
        const float* wr = W + lane*K;
        for (int k=0;k<K;k++) acc = fmaf(sx[w][k], wr[k], acc);
        int o = (t*BB+b)*DD + lane;
        g_mod[mod][o] = acc;
        if (mod==0){ g_h[0][o]=acc; g_h[1][o]=acc; }  // h starts as pl for both streams
    }
}

// ---------------- 2. precompute K,V for all (stream,layer), warp-per-row --
__global__ void k_kv(const float* __restrict__ in_w, const float* __restrict__ in_b,
                     const float* __restrict__ n1g, const float* __restrict__ n1b){
    int w = threadIdx.x >> 5, lane = threadIdx.x & 31;
    int idx = blockIdx.x*4 + w;           // 2*L*T*B rows
    int b = idx % BB; idx /= BB;
    int t = idx % TT; idx /= TT;
    int l = idx % LL; int s = idx / LL;
    int ksrc = (s==0)?1:2, vsrc=(s==0)?2:1;
    __shared__ float sK[4][DD], sV[4][DD];
    int d = lane;
    int ro = (t*BB+b)*DD;
    float kv = (d<DD)? g_mod[ksrc][ro+d] : 0.f;
    float vv = (d<DD)? g_mod[vsrc][ro+d] : 0.f;
    float ksum = warpsum(kv), ksq = warpsum(kv*kv);
    float vsum = warpsum(vv), vsq = warpsum(vv*vv);
    float km = ksum*(1.f/DD), kvar = ksq*(1.f/DD) - km*km;
    float vm = vsum*(1.f/DD), vvar = vsq*(1.f/DD) - vm*vm;
    float krs = rsqrtf(kvar+1e-5f), vrs = rsqrtf(vvar+1e-5f);
    int pb = (s*LL+l)*DD;
    if (d<DD){
        float g = n1g[pb+d], be = n1b[pb+d];
        sK[w][d] = (kv-km)*krs*g + be;
        sV[w][d] = (vv-vm)*vrs*g + be;
    }
    __syncwarp();
    if (d<DD){
        const float* iw = in_w + (s*LL+l)*3*DD*DD;
        const float* ib = in_b + (s*LL+l)*3*DD;
        float ka = ib[DD+d], va = ib[2*DD+d];
        const float* wk = iw + (DD+d)*DD;
        const float* wv = iw + (2*DD+d)*DD;
        #pragma unroll
        for (int j=0;j<DD;j++){ ka = fmaf(sK[w][j], wk[j], ka); va = fmaf(sV[w][j], wv[j], va); }
        int i = b*HH + d/HDD, e = d%HDD;
        int o = (i*TT + t)*HDD + e;
        g_K[s][l][o] = ka;
        g_V[s][l][o] = va;
    }
}

// ---------------- 2b. vbar = mean over t of V -----------------------------
__global__ void k_vbar(){
    int idx = blockIdx.x;                 // 2*L*NI blocks
    int i = idx % NI; idx /= NI;
    int l = idx % LL; int s = idx / LL;
    int e = threadIdx.x;
    if (e < HDD){
        float acc = 0.f;
        const float* v = g_V[s][l] + i*TT*HDD + e;
        for (int t=0;t<TT;t++) acc += v[t*HDD];
        g_vbar[s][l][i*HDD+e] = acc * (1.f/TT);
    }
}

// ---------------- 3. layer-0 Q projection, warp-per-row -------------------
__global__ void k_q0(const float* __restrict__ in_w, const float* __restrict__ in_b,
                     const float* __restrict__ n1g, const float* __restrict__ n1b){
    int w = threadIdx.x >> 5, lane = threadIdx.x & 31;
    int idx = blockIdx.x*4 + w;           // 2*T*B rows
    int b = idx % BB; idx /= BB;
    int t = idx % TT; int s = idx / TT;
    __shared__ float sX[4][DD];
    int ro = (t*BB+b)*DD;
    float x = (lane<DD)? g_h[s][ro+lane] : 0.f;
    float sum = warpsum(x), sq = warpsum(x*x);
    float m = sum*(1.f/DD), var = sq*(1.f/DD)-m*m, r = rsqrtf(var+1e-5f);
    int pb = (s*LL+0)*DD;
    if (lane<DD) sX[w][lane] = (x-m)*r*n1g[pb+lane] + n1b[pb+lane];
    __syncwarp();
    if (lane<DD){
        const float* iw = in_w + (s*LL+0)*3*DD*DD + lane*DD;
        float acc = in_b[(s*LL+0)*3*DD + lane];
        #pragma unroll
        for (int j=0;j<DD;j++) acc = fmaf(sX[w][j], iw[j], acc);
        acc *= 0.4082482904638631f;       // HD^-0.5
        int i = b*HH + lane/HDD, e = lane%HDD;
        g_Q[s][(i*TT+t)*HDD+e] = acc;
    }
}

// ---------------- 4. attention core (f32x2, hot kernel) -------------------
// One block per (s, i, 6-a group). 160 threads, thread = one b (key index).
// fused[a,b] = max_c (q_a o k_b) . (v_c + vbar)   [mean folded into max]
// then softmax over b and attn[a,:] = sum_b p_b * q_b
__global__ void __launch_bounds__(160) k_att(int l){
    int s = blockIdx.z, i = blockIdx.y, a0 = blockIdx.x*AA;
    int tid = threadIdx.x;
    __shared__ __align__(16) float2 sVd[TT][8];   // v' duplicated pairs, 64B/row
    __shared__ float  sQa[AA*HDD];
    __shared__ float  sred[5*8];
    const float* Kp = g_K[s][l] + i*TT*HDD;
    const float* Vp = g_V[s][l] + i*TT*HDD;
    const float* Qp = g_Q[s]    + i*TT*HDD;
    const float* vb = g_vbar[s][l] + i*HDD;
    for (int j=tid; j<TT*HDD; j+=160){
        int c = j/HDD, e = j - c*HDD;
        float v = Vp[j] + vb[e];
        sVd[c][e] = make_float2(v, v);
    }
    if (tid < AA*HDD) sQa[tid] = Qp[a0*HDD + tid];
    __syncthreads();

    bool valid = tid < TT;
    int b = valid ? tid : 0;
    float kb[HDD], qb[HDD];
    #pragma unroll
    for (int e=0;e<HDD;e++){ kb[e]=Kp[b*HDD+e]; qb[e]=Qp[b*HDD+e]; }

    unsigned long long kq2[3][HDD];
    #pragma unroll
    for (int p=0;p<3;p++)
        #pragma unroll
        for (int e=0;e<HDD;e++)
            kq2[p][e] = pack2(sQa[(2*p)*HDD+e]*kb[e], sQa[(2*p+1)*HDD+e]*kb[e]);

    float mx[AA];
    #pragma unroll
    for (int a=0;a<AA;a++) mx[a] = -INFINITY;

    #pragma unroll 2
    for (int c=0;c<TT;c++){
        const ulonglong2* pv = (const ulonglong2*)&sVd[c][0];
        ulonglong2 w0 = pv[0], w1 = pv[1], w2 = pv[2];
        #pragma unroll
        for (int p=0;p<3;p++){
            unsigned long long sc = mul2(kq2[p][0], w0.x);
            sc = fma2(kq2[p][1], w0.y, sc);
            sc = fma2(kq2[p][2], w1.x, sc);
            sc = fma2(kq2[p][3], w1.y, sc);
            sc = fma2(kq2[p][4], w2.x, sc);
            sc = fma2(kq2[p][5], w2.y, sc);
            float lo, hi; unpack2(sc, lo, hi);
            mx[2*p]   = fmaxf(mx[2*p],   lo);
            mx[2*p+1] = fmaxf(mx[2*p+1], hi);
        }
    }

    int b_ = i/HH, h_ = i%HH;
    #pragma unroll 1
    for (int a=0;a<AA;a++){
        float fused = valid ? mx[a] : -INFINITY;
        // block max over b
        float m = fused;
        #pragma unroll
        for (int o=16;o>0;o>>=1) m = fmaxf(m, __shfl_xor_sync(0xffffffffu, m, o));
        if ((tid&31)==0) sred[tid>>5] = m;
        __syncthreads();
        m = fmaxf(fmaxf(sred[0],sred[1]), fmaxf(fmaxf(sred[2],sred[3]), sred[4]));
        __syncthreads();
        float ex = __expf(fused - m);      // invalid lanes: exp(-inf)=0
        float vals[7];
        #pragma unroll
        for (int e=0;e<HDD;e++) vals[e] = ex*qb[e];
        vals[6] = ex;
        #pragma unroll
        for (int j=0;j<7;j++){
            float v = vals[j];
            #pragma unroll
            for (int o=16;o>0;o>>=1) v += __shfl_xor_sync(0xffffffffu, v, o);
            if ((tid&31)==0) sred[(tid>>5)*8 + j] = v;
        }
        __syncthreads();
        if (tid < HDD){
            float num=0.f, den=0.f;
            #pragma unroll
            for (int ww=0;ww<5;ww++){ num += sred[ww*8+tid]; den += sred[ww*8+6]; }
            g_attn[s][((a0+a)*BB + b_)*DD + h_*HDD + tid] = num/den;
        }
        __syncthreads();
    }
}

// ---------------- 5. out-proj + residual + LN + FFN + residual + Q(l+1) --
__global__ void k_ffnq(const float* __restrict__ out_w, const float* __restrict__ out_b,
                       const float* __restrict__ w1, const float* __restrict__ b1,
                       const float* __restrict__ w2, const float* __restrict__ b2,
                       const float* __restrict__ n2g, const float* __restrict__ n2b,
                       const float* __restrict__ in_w, const float* __restrict__ in_b,
                       const float* __restrict__ n1g, const float* __restrict__ n1b, int l){
    int w = threadIdx.x >> 5, lane = threadIdx.x & 31;
    int idx = blockIdx.x*4 + w;           // 2*T*B rows
    int b = idx % BB; idx /= BB;
    int t = idx % TT; int s = idx / TT;
    __shared__ float sA[4][DD], sXn[4][DD], sHid[4][4*DD];
    int ro = (t*BB+b)*DD;
    if (lane<DD) sA[w][lane] = g_attn[s][ro+lane];
    __syncwarp();
    int pl_ = s*LL+l;
    float x = 0.f;
    if (lane<DD){
        const float* wr = out_w + pl_*DD*DD + lane*DD;
        float acc = out_b[pl_*DD + lane];
        #pragma unroll
        for (int j=0;j<DD;j++) acc = fmaf(sA[w][j], wr[j], acc);
        x = g_h[s][ro+lane] + acc;        // residual
    }
    float sum = warpsum(x), sq = warpsum(x*x);
    float m = sum*(1.f/DD), var = sq*(1.f/DD)-m*m, r = rsqrtf(var+1e-5f);
    if (lane<DD) sXn[w][lane] = (x-m)*r*n2g[pl_*DD+lane] + n2b[pl_*DD+lane];
    __syncwarp();
    for (int j=lane; j<4*DD; j+=32){
        const float* wr = w1 + pl_*4*DD*DD + j*DD;
        float acc = b1[pl_*4*DD + j];
        #pragma unroll
        for (int q=0;q<DD;q++) acc = fmaf(sXn[w][q], wr[q], acc);
        sHid[w][j] = fmaxf(acc, 0.f);
    }
    __syncwarp();
    float hnew = 0.f;
    if (lane<DD){
        const float* wr = w2 + pl_*DD*4*DD + lane*4*DD;
        float acc = b2[pl_*DD + lane];
        #pragma unroll 4
        for (int j=0;j<4*DD;j++) acc = fmaf(sHid[w][j], wr[j], acc);
        hnew = x + acc;                   // residual 2
        g_h[s][ro+lane] = hnew;
    }
    if (l+1 < LL){
        // fused Q projection for next layer
        float sum2 = warpsum(hnew), sq2 = warpsum(hnew*hnew);
        float m2 = sum2*(1.f/DD), var2 = sq2*(1.f/DD)-m2*m2, r2 = rsqrtf(var2+1e-5f);
        int pb = (pl_+1)*DD;
        if (lane<DD) sA[w][lane] = (hnew-m2)*r2*n1g[pb+lane] + n1b[pb+lane];
        __syncwarp();
        if (lane<DD){
            const float* iw = in_w + (pl_+1)*3*DD*DD + lane*DD;
            float acc = in_b[(pl_+1)*3*DD + lane];
            #pragma unroll
            for (int j=0;j<DD;j++) acc = fmaf(sA[w][j], iw[j], acc);
            acc *= 0.4082482904638631f;
            int i = b*HH + lane/HDD, e = lane%HDD;
            g_Q[s][(i*TT+t)*HDD+e] = acc;
        }
    }
}

// ---------------- 6. head: concat last timestep, proj MLP, output --------
__global__ void k_head(const float* __restrict__ p1w, const float* __restrict__ p1b,
                       const float* __restrict__ p2w, const float* __restrict__ p2b,
                       const float* __restrict__ ow, const float* __restrict__ ob,
                       float* __restrict__ out){
    int tid = threadIdx.x;                // 64 threads
    __shared__ float sLast[BB*2*DD], sHid[2*DD], sC[2*DD];
    for (int idx=tid; idx<BB*2*DD; idx+=64){
        int b = idx/(2*DD), j = idx%(2*DD);
        float v = (j<DD) ? g_h[0][((TT-1)*BB+b)*DD + j]
                         : g_h[1][((TT-1)*BB+b)*DD + (j-DD)];
        sLast[idx] = v;
        out[BB + idx] = v;                // last_hs after out[0:8]
    }
    __syncthreads();
    for (int b=0;b<BB;b++){
        if (tid < 2*DD){
            float acc = p1b[tid];
            const float* wr = p1w + tid*2*DD;
            for (int j=0;j<2*DD;j++) acc = fmaf(sLast[b*2*DD+j], wr[j], acc);
            sHid[tid] = fmaxf(acc, 0.f);
        }
        __syncthreads();
        if (tid < 2*DD){
            float acc = p2b[tid];
            const float* wr = p2w + tid*2*DD;
            for (int j=0;j<2*DD;j++) acc = fmaf(sHid[j], wr[j], acc);
            acc += sLast[b*2*DD+tid];     // residual
            sC[tid] = acc * ow[tid];
        }
        __syncthreads();
        if (tid==0){
            float acc = ob[0];
            for (int j=0;j<2*DD;j++) acc += sC[j];
            out[b] = acc;
        }
        __syncthreads();
    }
}

// -------------------------------------------------------------------------
extern "C" void kernel_launch(void* const* d_in, const int* in_sizes, int n_in,
                              void* d_out, int out_size){
    const float* xl   = (const float*)d_in[0];
    const float* xa   = (const float*)d_in[1];
    const float* xv   = (const float*)d_in[2];
    const float* Wl   = (const float*)d_in[3];
    const float* Wa   = (const float*)d_in[4];
    const float* Wv   = (const float*)d_in[5];
    const float* in_w = (const float*)d_in[6];
    const float* in_b = (const float*)d_in[7];
    const float* outw = (const float*)d_in[8];
    const float* outb = (const float*)d_in[9];
    const float* l1w  = (const float*)d_in[10];
    const float* l1b  = (const float*)d_in[11];
    const float* l2w  = (const float*)d_in[12];
    const float* l2b  = (const float*)d_in[13];
    const float* n1g  = (const float*)d_in[14];
    const float* n1b  = (const float*)d_in[15];
    const float* n2g  = (const float*)d_in[16];
    const float* n2b  = (const float*)d_in[17];
    const float* p1w  = (const float*)d_in[18];
    const float* p1b  = (const float*)d_in[19];
    const float* p2w  = (const float*)d_in[20];
    const float* p2b  = (const float*)d_in[21];
    const float* ow   = (const float*)d_in[22];
    const float* ob   = (const float*)d_in[23];
    float* out = (float*)d_out;

    k_proj<<<dim3(TT*BB/4, 3), 128>>>(xl, xa, xv, Wl, Wa, Wv);
    k_kv<<<2*LL*TT*BB/4, 128>>>(in_w, in_b, n1g, n1b);
    k_vbar<<<2*LL*NI, 32>>>();
    k_q0<<<2*TT*BB/4, 128>>>(in_w, in_b, n1g, n1b);
    for (int l=0; l<LL; l++){
        k_att<<<dim3(TT/AA, NI, 2), 160>>>(l);
        k_ffnq<<<2*TT*BB/4, 128>>>(outw, outb, l1w, l1b, l2w, l2b, n2g, n2b,
                                   in_w, in_b, n1g, n1b, l);
    }
    k_head<<<1, 64>>>(p1w, p1b, p2w, p2b, ow, ob, out);
}

// round 3
// speedup vs baseline: 1.2091x; 1.2091x over previous
#include <cuda_runtime.h>
#include <cuda_fp16.h>
#include <math.h>

#define BB   8
#define TT   150
#define DD   30
#define HH   5
#define HDD  6
#define LL   3
#define NI   40     // BB*HH
#define KL   300
#define KA   74
#define KV   35
#define AA   6      // a-values per attention block (3 fp16x2 pairs)

// ---------------- device scratch (no allocations allowed) ----------------
__device__ float g_mod[3][TT*BB*DD];          // 0: pl, 1: pa, 2: pv   [T,B,D]
__device__ float g_h[2][TT*BB*DD];            // per-stream hidden state [T,B,D]
__device__ float g_K[2][LL][NI*TT*HDD];       // per (s,l): [i, t, e]
__device__ float g_V[2][LL][NI*TT*HDD];
__device__ float g_Q[2][NI*TT*HDD];           // current-layer Q
__device__ float g_attn[2][TT*BB*DD];         // attention output [T,B,D]

__device__ __forceinline__ float warpsum(float v){
    #pragma unroll
    for (int o=16;o>0;o>>=1) v += __shfl_xor_sync(0xffffffffu, v, o);
    return v;
}

// ---------------- 1. modality projections (conv1d k=1), warp-per-row -----
__global__ void k_proj(const float* __restrict__ xl, const float* __restrict__ xa,
                       const float* __restrict__ xv, const float* __restrict__ Wl,
                       const float* __restrict__ Wa, const float* __restrict__ Wv){
    int w = threadIdx.x >> 5, lane = threadIdx.x & 31;
    int r = blockIdx.x*4 + w;            // 0..T*B-1
    int mod = blockIdx.y;                // 0,1,2
    int t = r / BB, b = r % BB;
    const float *x, *W; int K;
    if (mod==0){x=xl;W=Wl;K=KL;} else if (mod==1){x=xa;W=Wa;K=KA;} else {x=xv;W=Wv;K=KV;}
    __shared__ float sx[4][KL];
    const float* xr = x + (b*TT + t)*K;
    for (int k=lane; k<K; k+=32) sx[w][k]=xr[k];
    __syncwarp();
    if (lane < DD){
        float acc = 0.f;
        const float* wr = W + lane*K;
        for (int k=0;k<K;k++) acc = fmaf(sx[w][k], wr[k], acc);
        int o = (t*BB+b)*DD + lane;
        g_mod[mod][o] = acc;
        if (mod==0){ g_h[0][o]=acc; g_h[1][o]=acc; }  // h starts as pl for both streams
    }
}

// ---------------- 2. precompute K,V for all (stream,layer), warp-per-row --
__global__ void k_kv(const float* __restrict__ in_w, const float* __restrict__ in_b,
                     const float* __restrict__ n1g, const float* __restrict__ n1b){
    int w = threadIdx.x >> 5, lane = threadIdx.x & 31;
    int idx = blockIdx.x*4 + w;           // 2*L*T*B rows
    int b = idx % BB; idx /= BB;
    int t = idx % TT; idx /= TT;
    int l = idx % LL; int s = idx / LL;
    int ksrc = (s==0)?1:2, vsrc=(s==0)?2:1;
    __shared__ float sK[4][DD], sV[4][DD];
    int d = lane;
    int ro = (t*BB+b)*DD;
    float kv = (d<DD)? g_mod[ksrc][ro+d] : 0.f;
    float vv = (d<DD)? g_mod[vsrc][ro+d] : 0.f;
    float ksum = warpsum(kv), ksq = warpsum(kv*kv);
    float vsum = warpsum(vv), vsq = warpsum(vv*vv);
    float km = ksum*(1.f/DD), kvar = ksq*(1.f/DD) - km*km;
    float vm = vsum*(1.f/DD), vvar = vsq*(1.f/DD) - vm*vm;
    float krs = rsqrtf(kvar+1e-5f), vrs = rsqrtf(vvar+1e-5f);
    int pb = (s*LL+l)*DD;
    if (d<DD){
        float g = n1g[pb+d], be = n1b[pb+d];
        sK[w][d] = (kv-km)*krs*g + be;
        sV[w][d] = (vv-vm)*vrs*g + be;
    }
    __syncwarp();
    if (d<DD){
        const float* iw = in_w + (s*LL+l)*3*DD*DD;
        const float* ib = in_b + (s*LL+l)*3*DD;
        float ka = ib[DD+d], va = ib[2*DD+d];
        const float* wk = iw + (DD+d)*DD;
        const float* wv = iw + (2*DD+d)*DD;
        #pragma unroll
        for (int j=0;j<DD;j++){ ka = fmaf(sK[w][j], wk[j], ka); va = fmaf(sV[w][j], wv[j], va); }
        int i = b*HH + d/HDD, e = d%HDD;
        int o = (i*TT + t)*HDD + e;
        g_K[s][l][o] = ka;
        g_V[s][l][o] = va;
    }
}

// ---------------- 3. layer-0 Q projection, warp-per-row -------------------
__global__ void k_q0(const float* __restrict__ in_w, const float* __restrict__ in_b,
                     const float* __restrict__ n1g, const float* __restrict__ n1b){
    int w = threadIdx.x >> 5, lane = threadIdx.x & 31;
    int idx = blockIdx.x*4 + w;           // 2*T*B rows
    int b = idx % BB; idx /= BB;
    int t = idx % TT; int s = idx / TT;
    __shared__ float sX[4][DD];
    int ro = (t*BB+b)*DD;
    float x = (lane<DD)? g_h[s][ro+lane] : 0.f;
    float sum = warpsum(x), sq = warpsum(x*x);
    float m = sum*(1.f/DD), var = sq*(1.f/DD)-m*m, r = rsqrtf(var+1e-5f);
    int pb = (s*LL+0)*DD;
    if (lane<DD) sX[w][lane] = (x-m)*r*n1g[pb+lane] + n1b[pb+lane];
    __syncwarp();
    if (lane<DD){
        const float* iw = in_w + (s*LL+0)*3*DD*DD + lane*DD;
        float acc = in_b[(s*LL+0)*3*DD + lane];
        #pragma unroll
        for (int j=0;j<DD;j++) acc = fmaf(sX[w][j], iw[j], acc);
        acc *= 0.4082482904638631f;       // HD^-0.5
        int i = b*HH + lane/HDD, e = lane%HDD;
        g_Q[s][(i*TT+t)*HDD+e] = acc;
    }
}

// ---------------- 4. attention core (fp16x2 HFMA2 scan, hot kernel) -------
// One block per (s, i, 6-a group). 160 threads, thread = one b (key index).
// fused[a,b] = (q_a o k_b).vbar  [fp32]  +  max_c (q_a o k_b).v_c  [fp16x2]
// then softmax over b and attn[a,:] = sum_b p_b * q_b
__global__ void __launch_bounds__(160) k_att(int l){
    int s = blockIdx.z, i = blockIdx.y, a0 = blockIdx.x*AA;
    int tid = threadIdx.x;
    __shared__ __align__(16) __half2 sVh[TT][8];  // v duplicated fp16 pairs, 32B/row
    __shared__ float  sQa[AA*HDD];
    __shared__ float  sVbarP[5][8];
    __shared__ float  sVbar[HDD];
    __shared__ float  sred[5*8];
    const float* Kp = g_K[s][l] + i*TT*HDD;
    const float* Vp = g_V[s][l] + i*TT*HDD;
    const float* Qp = g_Q[s]    + i*TT*HDD;
    bool valid = tid < TT;
    int b = valid ? tid : 0;
    int lane = tid & 31, w = tid >> 5;

    float kb[HDD], qb[HDD], vv[HDD];
    #pragma unroll
    for (int e=0;e<HDD;e++){
        kb[e] = Kp[b*HDD+e];
        qb[e] = Qp[b*HDD+e];
        vv[e] = valid ? Vp[b*HDD+e] : 0.f;
    }
    // fill fp16 duplicated V rows (thread owns row c = tid)
    if (valid){
        #pragma unroll
        for (int e=0;e<HDD;e++) sVh[tid][e] = __float2half2_rn(vv[e]);
    }
    if (tid < AA*HDD) sQa[tid] = Qp[a0*HDD + tid];
    // vbar = mean over c of v (block reduction, fp32)
    {
        float p[HDD];
        #pragma unroll
        for (int e=0;e<HDD;e++) p[e] = warpsum(vv[e]);
        if (lane==0){
            #pragma unroll
            for (int e=0;e<HDD;e++) sVbarP[w][e] = p[e];
        }
    }
    __syncthreads();
    if (tid < HDD){
        float acc = 0.f;
        #pragma unroll
        for (int ww=0;ww<5;ww++) acc += sVbarP[ww][tid];
        sVbar[tid] = acc * (1.f/TT);
    }
    __syncthreads();

    // kq in fp16x2 (a-pairs), mean term in fp32
    __half2 kq[3][HDD];
    float mean_[AA];
    #pragma unroll
    for (int p=0;p<3;p++){
        float m0 = 0.f, m1 = 0.f;
        #pragma unroll
        for (int e=0;e<HDD;e++){
            float lo = sQa[(2*p)*HDD+e]   * kb[e];
            float hi = sQa[(2*p+1)*HDD+e] * kb[e];
            kq[p][e] = __floats2half2_rn(lo, hi);
            m0 = fmaf(lo, sVbar[e], m0);
            m1 = fmaf(hi, sVbar[e], m1);
        }
        mean_[2*p] = m0; mean_[2*p+1] = m1;
    }

    __half2 mx2[3];
    #pragma unroll
    for (int p=0;p<3;p++) mx2[p] = __floats2half2_rn(-60000.f, -60000.f);

    #pragma unroll 2
    for (int c=0;c<TT;c++){
        uint4 u0 = *reinterpret_cast<const uint4*>(&sVh[c][0]);
        uint2 u1 = *reinterpret_cast<const uint2*>(&sVh[c][4]);
        __half2 v0 = *(__half2*)&u0.x, v1 = *(__half2*)&u0.y;
        __half2 v2 = *(__half2*)&u0.z, v3 = *(__half2*)&u0.w;
        __half2 v4 = *(__half2*)&u1.x, v5 = *(__half2*)&u1.y;
        #pragma unroll
        for (int p=0;p<3;p++){
            __half2 acc = __hmul2(kq[p][0], v0);
            acc = __hfma2(kq[p][1], v1, acc);
            acc = __hfma2(kq[p][2], v2, acc);
            acc = __hfma2(kq[p][3], v3, acc);
            acc = __hfma2(kq[p][4], v4, acc);
            acc = __hfma2(kq[p][5], v5, acc);
            mx2[p] = __hmax2(mx2[p], acc);
        }
    }
    float mx[AA];
    #pragma unroll
    for (int p=0;p<3;p++){
        mx[2*p]   = __low2float(mx2[p]);
        mx[2*p+1] = __high2float(mx2[p]);
    }

    int b_ = i/HH, h_ = i%HH;
    #pragma unroll 1
    for (int a=0;a<AA;a++){
        float fused = valid ? (mean_[a] + mx[a]) : -INFINITY;
        // block max over b
        float m = fused;
        #pragma unroll
        for (int o=16;o>0;o>>=1) m = fmaxf(m, __shfl_xor_sync(0xffffffffu, m, o));
        if (lane==0) sred[w] = m;
        __syncthreads();
        m = fmaxf(fmaxf(sred[0],sred[1]), fmaxf(fmaxf(sred[2],sred[3]), sred[4]));
        __syncthreads();
        float ex = __expf(fused - m);      // invalid lanes: exp(-inf)=0
        float vals[7];
        #pragma unroll
        for (int e=0;e<HDD;e++) vals[e] = ex*qb[e];
        vals[6] = ex;
        #pragma unroll
        for (int j=0;j<7;j++){
            float v = vals[j];
            #pragma unroll
            for (int o=16;o>0;o>>=1) v += __shfl_xor_sync(0xffffffffu, v, o);
            if (lane==0) sred[w*8 + j] = v;
        }
        __syncthreads();
        if (tid < HDD){
            float num=0.f, den=0.f;
            #pragma unroll
            for (int ww=0;ww<5;ww++){ num += sred[ww*8+tid]; den += sred[ww*8+6]; }
            g_attn[s][((a0+a)*BB + b_)*DD + h_*HDD + tid] = num/den;
        }
        __syncthreads();
    }
}

// ---------------- 5. out-proj + residual + LN + FFN + residual + Q(l+1) --
__global__ void k_ffnq(const float* __restrict__ out_w, const float* __restrict__ out_b,
                       const float* __restrict__ w1, const float* __restrict__ b1,
                       const float* __restrict__ w2, const float* __restrict__ b2,
                       const float* __restrict__ n2g, const float* __restrict__ n2b,
                       const float* __restrict__ in_w, const float* __restrict__ in_b,
                       const float* __restrict__ n1g, const float* __restrict__ n1b, int l){
    int w = threadIdx.x >> 5, lane = threadIdx.x & 31;
    int idx = blockIdx.x*4 + w;           // 2*T*B rows
    int b = idx % BB; idx /= BB;
    int t = idx % TT; int s = idx / TT;
    __shared__ float sA[4][DD], sXn[4][DD], sHid[4][4*DD];
    int ro = (t*BB+b)*DD;
    if (lane<DD) sA[w][lane] = g_attn[s][ro+lane];
    __syncwarp();
    int pl_ = s*LL+l;
    float x = 0.f;
    if (lane<DD){
        const float* wr = out_w + pl_*DD*DD + lane*DD;
        float acc = out_b[pl_*DD + lane];
        #pragma unroll
        for (int j=0;j<DD;j++) acc = fmaf(sA[w][j], wr[j], acc);
        x = g_h[s][ro+lane] + acc;        // residual
    }
    float sum = warpsum(x), sq = warpsum(x*x);
    float m = sum*(1.f/DD), var = sq*(1.f/DD)-m*m, r = rsqrtf(var+1e-5f);
    if (lane<DD) sXn[w][lane] = (x-m)*r*n2g[pl_*DD+lane] + n2b[pl_*DD+lane];
    __syncwarp();
    for (int j=lane; j<4*DD; j+=32){
        const float* wr = w1 + pl_*4*DD*DD + j*DD;
        float acc = b1[pl_*4*DD + j];
        #pragma unroll
        for (int q=0;q<DD;q++) acc = fmaf(sXn[w][q], wr[q], acc);
        sHid[w][j] = fmaxf(acc, 0.f);
    }
    __syncwarp();
    float hnew = 0.f;
    if (lane<DD){
        const float* wr = w2 + pl_*DD*4*DD + lane*4*DD;
        float acc = b2[pl_*DD + lane];
        #pragma unroll 4
        for (int j=0;j<4*DD;j++) acc = fmaf(sHid[w][j], wr[j], acc);
        hnew = x + acc;                   // residual 2
        g_h[s][ro+lane] = hnew;
    }
    if (l+1 < LL){
        // fused Q projection for next layer
        float sum2 = warpsum(hnew), sq2 = warpsum(hnew*hnew);
        float m2 = sum2*(1.f/DD), var2 = sq2*(1.f/DD)-m2*m2, r2 = rsqrtf(var2+1e-5f);
        int pb = (pl_+1)*DD;
        if (lane<DD) sA[w][lane] = (hnew-m2)*r2*n1g[pb+lane] + n1b[pb+lane];
        __syncwarp();
        if (lane<DD){
            const float* iw = in_w + (pl_+1)*3*DD*DD + lane*DD;
            float acc = in_b[(pl_+1)*3*DD + lane];
            #pragma unroll
            for (int j=0;j<DD;j++) acc = fmaf(sA[w][j], iw[j], acc);
            acc *= 0.4082482904638631f;
            int i = b*HH + lane/HDD, e = lane%HDD;
            g_Q[s][(i*TT+t)*HDD+e] = acc;
        }
    }
}

// ---------------- 6. head: concat last timestep, proj MLP, output --------
__global__ void k_head(const float* __restrict__ p1w, const float* __restrict__ p1b,
                       const float* __restrict__ p2w, const float* __restrict__ p2b,
                       const float* __restrict__ ow, const float* __restrict__ ob,
                       float* __restrict__ out){
    int tid = threadIdx.x;                // 64 threads
    __shared__ float sLast[BB*2*DD], sHid[2*DD], sC[2*DD];
    for (int idx=tid; idx<BB*2*DD; idx+=64){
        int b = idx/(2*DD), j = idx%(2*DD);
        float v = (j<DD) ? g_h[0][((TT-1)*BB+b)*DD + j]
                         : g_h[1][((TT-1)*BB+b)*DD + (j-DD)];
        sLast[idx] = v;
        out[BB + idx] = v;                // last_hs after out[0:8]
    }
    __syncthreads();
    for (int b=0;b<BB;b++){
        if (tid < 2*DD){
            float acc = p1b[tid];
            const float* wr = p1w + tid*2*DD;
            for (int j=0;j<2*DD;j++) acc = fmaf(sLast[b*2*DD+j], wr[j], acc);
            sHid[tid] = fmaxf(acc, 0.f);
        }
        __syncthreads();
        if (tid < 2*DD){
            float acc = p2b[tid];
            const float* wr = p2w + tid*2*DD;
            for (int j=0;j<2*DD;j++) acc = fmaf(sHid[j], wr[j], acc);
            acc += sLast[b*2*DD+tid];     // residual
            sC[tid] = acc * ow[tid];
        }
        __syncthreads();
        if (tid==0){
            float acc = ob[0];
            for (int j=0;j<2*DD;j++) acc += sC[j];
            out[b] = acc;
        }
        __syncthreads();
    }
}

// -------------------------------------------------------------------------
extern "C" void kernel_launch(void* const* d_in, const int* in_sizes, int n_in,
                              void* d_out, int out_size){
    const float* xl   = (const float*)d_in[0];
    const float* xa   = (const float*)d_in[1];
    const float* xv   = (const float*)d_in[2];
    const float* Wl   = (const float*)d_in[3];
    const float* Wa   = (const float*)d_in[4];
    const float* Wv   = (const float*)d_in[5];
    const float* in_w = (const float*)d_in[6];
    const float* in_b = (const float*)d_in[7];
    const float* outw = (const float*)d_in[8];
    const float* outb = (const float*)d_in[9];
    const float* l1w  = (const float*)d_in[10];
    const float* l1b  = (const float*)d_in[11];
    const float* l2w  = (const float*)d_in[12];
    const float* l2b  = (const float*)d_in[13];
    const float* n1g  = (const float*)d_in[14];
    const float* n1b  = (const float*)d_in[15];
    const float* n2g  = (const float*)d_in[16];
    const float* n2b  = (const float*)d_in[17];
    const float* p1w  = (const float*)d_in[18];
    const float* p1b  = (const float*)d_in[19];
    const float* p2w  = (const float*)d_in[20];
    const float* p2b  = (const float*)d_in[21];
    const float* ow   = (const float*)d_in[22];
    const float* ob   = (const float*)d_in[23];
    float* out = (float*)d_out;

    k_proj<<<dim3(TT*BB/4, 3), 128>>>(xl, xa, xv, Wl, Wa, Wv);
    k_kv<<<2*LL*TT*BB/4, 128>>>(in_w, in_b, n1g, n1b);
    k_q0<<<2*TT*BB/4, 128>>>(in_w, in_b, n1g, n1b);
    for (int l=0; l<LL; l++){
        k_att<<<dim3(TT/AA, NI, 2), 160>>>(l);
        k_ffnq<<<2*TT*BB/4, 128>>>(outw, outb, l1w, l1b, l2w, l2b, n2g, n2b,
                                   in_w, in_b, n1g, n1b, l);
    }
    k_head<<<1, 64>>>(p1w, p1b, p2w, p2b, ow, ob, out);
}

// round 4
// speedup vs baseline: 1.3511x; 1.1175x over previous
#include <cuda_runtime.h>
#include <cuda_fp16.h>
#include <math.h>

#define BB   8
#define TT   150
#define DD   30
#define HH   5
#define HDD  6
#define LL   3
#define NI   40     // BB*HH
#define KL   300
#define KA   74
#define KV   35
#define AA   10     // a-values per attention block (5 fp16x2 pairs)

// ---------------- device scratch (no allocations allowed) ----------------
__device__ float g_h[2][TT*BB*DD];            // per-stream hidden state [T,B,D]
__device__ float g_K[2][LL][NI*TT*HDD];       // per (s,l): [i, t, e]
__device__ float g_V[2][LL][NI*TT*HDD];
__device__ float g_Q[2][NI*TT*HDD];           // current-layer Q
__device__ float g_attn[2][TT*BB*DD];         // attention output [T,B,D]

__device__ __forceinline__ float warpsum(float v){
    #pragma unroll
    for (int o=16;o>0;o>>=1) v += __shfl_xor_sync(0xffffffffu, v, o);
    return v;
}

// ---------------- 1. fused pre-stage: proj + all K/V + Q(l=0) -------------
// one block per (t,b); everything is row-local.
__global__ void __launch_bounds__(96) k_pre(
    const float* __restrict__ xl, const float* __restrict__ xa,
    const float* __restrict__ xv, const float* __restrict__ Wl,
    const float* __restrict__ Wa, const float* __restrict__ Wv,
    const float* __restrict__ in_w, const float* __restrict__ in_b,
    const float* __restrict__ n1g, const float* __restrict__ n1b){
    int r = blockIdx.x;                  // 0..T*B-1
    int t = r / BB, b = r % BB;
    int w = threadIdx.x >> 5, lane = threadIdx.x & 31;
    __shared__ float sx[KL+KA+KV];
    __shared__ float xn[3][DD];
    __shared__ float axk[DD], axv[DD], axq[DD];
    for (int k=threadIdx.x; k<KL; k+=96) sx[k]        = xl[(b*TT+t)*KL + k];
    for (int k=threadIdx.x; k<KA; k+=96) sx[KL+k]     = xa[(b*TT+t)*KA + k];
    for (int k=threadIdx.x; k<KV; k+=96) sx[KL+KA+k]  = xv[(b*TT+t)*KV + k];
    __syncthreads();
    // modality projection: warp w -> mod w
    float pv = 0.f;
    {
        const float* W  = (w==0)? Wl : (w==1)? Wa : Wv;
        int K           = (w==0)? KL : (w==1)? KA : KV;
        const float* xs = sx + ((w==0)? 0 : (w==1)? KL : KL+KA);
        if (lane < DD){
            const float* wr = W + lane*K;
            for (int k=0;k<K;k++) pv = fmaf(xs[k], wr[k], pv);
            if (w==0){ int o=(t*BB+b)*DD+lane; g_h[0][o]=pv; g_h[1][o]=pv; }
        }
    }
    // LN normalize (no affine yet)
    {
        float x = (lane<DD)? pv : 0.f;
        float sum = warpsum(x), sq = warpsum(x*x);
        float m = sum*(1.f/DD), var = sq*(1.f/DD)-m*m, rs = rsqrtf(var+1e-5f);
        if (lane<DD) xn[w][lane] = (x-m)*rs;
    }
    __syncthreads();
    #pragma unroll 1
    for (int sl=0; sl<6; sl++){
        int s_ = sl/LL, l_ = sl%LL;
        int ksrc = (s_==0)?1:2, vsrc = (s_==0)?2:1;
        int pb = sl*DD;
        if (lane<DD){
            float g = n1g[pb+lane], be = n1b[pb+lane];
            if (w==0) axk[lane] = xn[ksrc][lane]*g + be;
            else if (w==1) axv[lane] = xn[vsrc][lane]*g + be;
            else if (l_==0) axq[lane] = xn[0][lane]*g + be;
        }
        __syncthreads();
        if (lane<DD){
            const float* iw = in_w + sl*3*DD*DD;
            const float* ib = in_b + sl*3*DD;
            int i = b*HH + lane/HDD, e = lane%HDD;
            int o = (i*TT + t)*HDD + e;
            if (w==0){
                float acc = ib[DD+lane];
                const float* wr = iw + (DD+lane)*DD;
                #pragma unroll
                for (int j=0;j<DD;j++) acc = fmaf(axk[j], wr[j], acc);
                g_K[s_][l_][o] = acc;
            } else if (w==1){
                float acc = ib[2*DD+lane];
                const float* wr = iw + (2*DD+lane)*DD;
                #pragma unroll
                for (int j=0;j<DD;j++) acc = fmaf(axv[j], wr[j], acc);
                g_V[s_][l_][o] = acc;
            } else if (l_==0){
                float acc = ib[lane];
                const float* wr = iw + lane*DD;
                #pragma unroll
                for (int j=0;j<DD;j++) acc = fmaf(axq[j], wr[j], acc);
                g_Q[s_][o] = acc * 0.4082482904638631f;
            }
        }
        __syncthreads();
    }
}

// ---------------- 2. attention core (fp16x2 HFMA2 scan, hot kernel) -------
// One block per (s, i, 10-a group). 160 threads, thread = one b (key index).
// fused[a,b] = max_c (q_a o k_b) . (v_c + vbar)     [mean folded into max]
// then softmax over b and attn[a,:] = sum_b p_b * q_b
__global__ void __launch_bounds__(160) k_att(int l){
    int s = blockIdx.z, i = blockIdx.y, a0 = blockIdx.x*AA;
    int tid = threadIdx.x;
    int lane = tid & 31, w = tid >> 5;
    __shared__ __align__(16) __half2 sVh[TT][8];  // v' duplicated fp16 pairs
    __shared__ float sQa[AA*HDD];
    __shared__ float sP[5][8];
    __shared__ float sVbar[HDD];
    __shared__ float sMax[AA][5];
    __shared__ float sBMax[AA];
    __shared__ float sSum[AA][5][8];
    const float* Kp = g_K[s][l] + i*TT*HDD;
    const float* Vp = g_V[s][l] + i*TT*HDD;
    const float* Qp = g_Q[s]    + i*TT*HDD;
    bool valid = tid < TT;
    int b = valid ? tid : 0;

    float kb[HDD], vv[HDD];
    #pragma unroll
    for (int e=0;e<HDD;e++){
        kb[e] = Kp[b*HDD+e];
        vv[e] = valid ? Vp[b*HDD+e] : 0.f;
    }
    {   // vbar partials
        float p[HDD];
        #pragma unroll
        for (int e=0;e<HDD;e++) p[e] = warpsum(vv[e]);
        if (lane==0){
            #pragma unroll
            for (int e=0;e<HDD;e++) sP[w][e] = p[e];
        }
    }
    if (tid < AA*HDD) sQa[tid] = Qp[a0*HDD + tid];
    __syncthreads();
    if (tid < HDD){
        float acc = 0.f;
        #pragma unroll
        for (int ww=0;ww<5;ww++) acc += sP[ww][tid];
        sVbar[tid] = acc * (1.f/TT);
    }
    __syncthreads();
    if (valid){
        #pragma unroll
        for (int e=0;e<HDD;e++) sVh[tid][e] = __float2half2_rn(vv[e] + sVbar[e]);
    }
    __syncthreads();

    // kq in fp16x2 (a-pairs)
    __half2 kq[5][HDD];
    #pragma unroll
    for (int p=0;p<5;p++)
        #pragma unroll
        for (int e=0;e<HDD;e++)
            kq[p][e] = __floats2half2_rn(sQa[(2*p)*HDD+e]*kb[e],
                                         sQa[(2*p+1)*HDD+e]*kb[e]);

    __half2 mx2[5];
    #pragma unroll
    for (int p=0;p<5;p++) mx2[p] = __floats2half2_rn(-60000.f, -60000.f);

    #pragma unroll 2
    for (int c=0;c<TT;c++){
        uint4 u0 = *reinterpret_cast<const uint4*>(&sVh[c][0]);
        uint2 u1 = *reinterpret_cast<const uint2*>(&sVh[c][4]);
        __half2 v0 = *(__half2*)&u0.x, v1 = *(__half2*)&u0.y;
        __half2 v2 = *(__half2*)&u0.z, v3 = *(__half2*)&u0.w;
        __half2 v4 = *(__half2*)&u1.x, v5 = *(__half2*)&u1.y;
        #pragma unroll
        for (int p=0;p<5;p++){
            __half2 acc = __hmul2(kq[p][0], v0);
            acc = __hfma2(kq[p][1], v1, acc);
            acc = __hfma2(kq[p][2], v2, acc);
            acc = __hfma2(kq[p][3], v3, acc);
            acc = __hfma2(kq[p][4], v4, acc);
            acc = __hfma2(kq[p][5], v5, acc);
            mx2[p] = __hmax2(mx2[p], acc);
        }
    }
    float fx[AA];
    #pragma unroll
    for (int p=0;p<5;p++){
        fx[2*p]   = __low2float(mx2[p]);
        fx[2*p+1] = __high2float(mx2[p]);
    }

    // ---- batched epilogue: 3 syncs total ----
    #pragma unroll
    for (int a=0;a<AA;a++){
        float m = valid ? fx[a] : -INFINITY;
        #pragma unroll
        for (int o=16;o>0;o>>=1) m = fmaxf(m, __shfl_xor_sync(0xffffffffu, m, o));
        if (lane==0) sMax[a][w] = m;
    }
    __syncthreads();
    if (tid < AA){
        float m = sMax[tid][0];
        #pragma unroll
        for (int ww=1;ww<5;ww++) m = fmaxf(m, sMax[tid][ww]);
        sBMax[tid] = m;
    }
    __syncthreads();
    float qb[HDD];
    #pragma unroll
    for (int e=0;e<HDD;e++) qb[e] = Qp[b*HDD+e];
    #pragma unroll
    for (int a=0;a<AA;a++){
        float ex = valid ? __expf(fx[a] - sBMax[a]) : 0.f;
        float v7[7];
        #pragma unroll
        for (int e=0;e<HDD;e++) v7[e] = ex*qb[e];
        v7[6] = ex;
        #pragma unroll
        for (int j=0;j<7;j++){
            float v = v7[j];
            #pragma unroll
            for (int o=16;o>0;o>>=1) v += __shfl_xor_sync(0xffffffffu, v, o);
            if (lane==0) sSum[a][w][j] = v;
        }
    }
    __syncthreads();
    if (tid < AA*HDD){
        int a = tid / HDD, e = tid % HDD;
        float num=0.f, den=0.f;
        #pragma unroll
        for (int ww=0;ww<5;ww++){ num += sSum[a][ww][e]; den += sSum[a][ww][6]; }
        int b_ = i/HH, h_ = i%HH;
        g_attn[s][((a0+a)*BB + b_)*DD + h_*HDD + e] = num/den;
    }
}

// ---------------- 3. out-proj + residual + LN + FFN + residual + Q(l+1) --
__global__ void k_ffnq(const float* __restrict__ out_w, const float* __restrict__ out_b,
                       const float* __restrict__ w1, const float* __restrict__ b1,
                       const float* __restrict__ w2, const float* __restrict__ b2,
                       const float* __restrict__ n2g, const float* __restrict__ n2b,
                       const float* __restrict__ in_w, const float* __restrict__ in_b,
                       const float* __restrict__ n1g, const float* __restrict__ n1b, int l){
    int w = threadIdx.x >> 5, lane = threadIdx.x & 31;
    int idx = blockIdx.x*4 + w;           // 2*T*B rows
    int b = idx % BB; idx /= BB;
    int t = idx % TT; int s = idx / TT;
    __shared__ float sA[4][DD], sXn[4][DD], sHid[4][4*DD];
    int ro = (t*BB+b)*DD;
    if (lane<DD) sA[w][lane] = g_attn[s][ro+lane];
    __syncwarp();
    int pl_ = s*LL+l;
    float x = 0.f;
    if (lane<DD){
        const float* wr = out_w + pl_*DD*DD + lane*DD;
        float acc = out_b[pl_*DD + lane];
        #pragma unroll
        for (int j=0;j<DD;j++) acc = fmaf(sA[w][j], wr[j], acc);
        x = g_h[s][ro+lane] + acc;        // residual
    }
    float sum = warpsum(x), sq = warpsum(x*x);
    float m = sum*(1.f/DD), var = sq*(1.f/DD)-m*m, r = rsqrtf(var+1e-5f);
    if (lane<DD) sXn[w][lane] = (x-m)*r*n2g[pl_*DD+lane] + n2b[pl_*DD+lane];
    __syncwarp();
    for (int j=lane; j<4*DD; j+=32){
        const float* wr = w1 + pl_*4*DD*DD + j*DD;
        float acc = b1[pl_*4*DD + j];
        #pragma unroll
        for (int q=0;q<DD;q++) acc = fmaf(sXn[w][q], wr[q], acc);
        sHid[w][j] = fmaxf(acc, 0.f);
    }
    __syncwarp();
    float hnew = 0.f;
    if (lane<DD){
        const float* wr = w2 + pl_*DD*4*DD + lane*4*DD;
        float acc = b2[pl_*DD + lane];
        #pragma unroll 4
        for (int j=0;j<4*DD;j++) acc = fmaf(sHid[w][j], wr[j], acc);
        hnew = x + acc;                   // residual 2
        g_h[s][ro+lane] = hnew;
    }
    if (l+1 < LL){
        // fused Q projection for next layer
        float sum2 = warpsum(hnew), sq2 = warpsum(hnew*hnew);
        float m2 = sum2*(1.f/DD), var2 = sq2*(1.f/DD)-m2*m2, r2 = rsqrtf(var2+1e-5f);
        int pb = (pl_+1)*DD;
        if (lane<DD) sA[w][lane] = (hnew-m2)*r2*n1g[pb+lane] + n1b[pb+lane];
        __syncwarp();
        if (lane<DD){
            const float* iw = in_w + (pl_+1)*3*DD*DD + lane*DD;
            float acc = in_b[(pl_+1)*3*DD + lane];
            #pragma unroll
            for (int j=0;j<DD;j++) acc = fmaf(sA[w][j], iw[j], acc);
            acc *= 0.4082482904638631f;
            int i = b*HH + lane/HDD, e = lane%HDD;
            g_Q[s][(i*TT+t)*HDD+e] = acc;
        }
    }
}

// ---------------- 4. head: concat last timestep, proj MLP, output --------
__global__ void k_head(const float* __restrict__ p1w, const float* __restrict__ p1b,
                       const float* __restrict__ p2w, const float* __restrict__ p2b,
                       const float* __restrict__ ow, const float* __restrict__ ob,
                       float* __restrict__ out){
    int tid = threadIdx.x;                // 64 threads
    __shared__ float sLast[BB*2*DD], sHid[2*DD], sC[2*DD];
    for (int idx=tid; idx<BB*2*DD; idx+=64){
        int b = idx/(2*DD), j = idx%(2*DD);
        float v = (j<DD) ? g_h[0][((TT-1)*BB+b)*DD + j]
                         : g_h[1][((TT-1)*BB+b)*DD + (j-DD)];
        sLast[idx] = v;
        out[BB + idx] = v;                // last_hs after out[0:8]
    }
    __syncthreads();
    for (int b=0;b<BB;b++){
        if (tid < 2*DD){
            float acc = p1b[tid];
            const float* wr = p1w + tid*2*DD;
            for (int j=0;j<2*DD;j++) acc = fmaf(sLast[b*2*DD+j], wr[j], acc);
            sHid[tid] = fmaxf(acc, 0.f);
        }
        __syncthreads();
        if (tid < 2*DD){
            float acc = p2b[tid];
            const float* wr = p2w + tid*2*DD;
            for (int j=0;j<2*DD;j++) acc = fmaf(sHid[j], wr[j], acc);
            acc += sLast[b*2*DD+tid];     // residual
            sC[tid] = acc * ow[tid];
        }
        __syncthreads();
        if (tid==0){
            float acc = ob[0];
            for (int j=0;j<2*DD;j++) acc += sC[j];
            out[b] = acc;
        }
        __syncthreads();
    }
}

// -------------------------------------------------------------------------
extern "C" void kernel_launch(void* const* d_in, const int* in_sizes, int n_in,
                              void* d_out, int out_size){
    const float* xl   = (const float*)d_in[0];
    const float* xa   = (const float*)d_in[1];
    const float* xv   = (const float*)d_in[2];
    const float* Wl   = (const float*)d_in[3];
    const float* Wa   = (const float*)d_in[4];
    const float* Wv   = (const float*)d_in[5];
    const float* in_w = (const float*)d_in[6];
    const float* in_b = (const float*)d_in[7];
    const float* outw = (const float*)d_in[8];
    const float* outb = (const float*)d_in[9];
    const float* l1w  = (const float*)d_in[10];
    const float* l1b  = (const float*)d_in[11];
    const float* l2w  = (const float*)d_in[12];
    const float* l2b  = (const float*)d_in[13];
    const float* n1g  = (const float*)d_in[14];
    const float* n1b  = (const float*)d_in[15];
    const float* n2g  = (const float*)d_in[16];
    const float* n2b  = (const float*)d_in[17];
    const float* p1w  = (const float*)d_in[18];
    const float* p1b  = (const float*)d_in[19];
    const float* p2w  = (const float*)d_in[20];
    const float* p2b  = (const float*)d_in[21];
    const float* ow   = (const float*)d_in[22];
    const float* ob   = (const float*)d_in[23];
    float* out = (float*)d_out;

    k_pre<<<TT*BB, 96>>>(xl, xa, xv, Wl, Wa, Wv, in_w, in_b, n1g, n1b);
    for (int l=0; l<LL; l++){
        k_att<<<dim3(TT/AA, NI, 2), 160>>>(l);
        k_ffnq<<<2*TT*BB/4, 128>>>(outw, outb, l1w, l1b, l2w, l2b, n2g, n2b,
                                   in_w, in_b, n1g, n1b, l);
    }
    k_head<<<1, 64>>>(p1w, p1b, p2w, p2b, ow, ob, out);
}